// round 16
// baseline (speedup 1.0000x reference)
#include <cuda_runtime.h>

// Problem constants
#define Bn  2
#define Tn  4096
#define Dn  512
#define Hn  8
#define DHn 64
#define BHn (Bn*Hn)

typedef unsigned char uchar;

// Scratch (device globals: no allocation allowed)
__device__ float g_Q [BHn*Tn*DHn];   // [bh][t][dh]   pre-scaled(1/8) + tf32-rounded
__device__ float g_K [BHn*Tn*DHn];   // [bh][t][dh]   tf32-rounded
__device__ float g_V [BHn*DHn*Tn];   // [bh][dh][t]   TRANSPOSED + tf32-rounded
__device__ float g_AO[Bn*Tn*Dn];     // [b][t][d]  attention output, pre-Wo
__device__ unsigned g_mbits[(size_t)Tn*Tn/32];  // bit-packed mask
__device__ int g_mask_mode;                     // 0=uint8, 1=int32, 2=float32

// ---- tf32 / mma / ldmatrix / cp.async helpers ------------------------------
__device__ __forceinline__ float tf32r(float x) {
    float r; asm("cvt.rna.tf32.f32 %0, %1;" : "=f"(r) : "f"(x)); return r;
}
__device__ __forceinline__ void mma_tf32(float c[4],
    unsigned a0, unsigned a1, unsigned a2, unsigned a3, unsigned b0, unsigned b1)
{
    asm volatile(
        "mma.sync.aligned.m16n8k8.row.col.f32.tf32.tf32.f32 "
        "{%0,%1,%2,%3}, {%4,%5,%6,%7}, {%8,%9}, {%0,%1,%2,%3};"
        : "+f"(c[0]), "+f"(c[1]), "+f"(c[2]), "+f"(c[3])
        : "r"(a0), "r"(a1), "r"(a2), "r"(a3), "r"(b0), "r"(b1));
}
__device__ __forceinline__ void ldsm4(unsigned &d0, unsigned &d1, unsigned &d2, unsigned &d3,
                                      unsigned addr)
{
    asm volatile("ldmatrix.sync.aligned.m8n8.x4.shared.b16 {%0,%1,%2,%3}, [%4];"
        : "=r"(d0), "=r"(d1), "=r"(d2), "=r"(d3) : "r"(addr));
}
__device__ __forceinline__ unsigned sm_u32(const void* p) {
    return (unsigned)__cvta_generic_to_shared(p);
}
__device__ __forceinline__ unsigned fbits(float x) { return __float_as_uint(x); }
__device__ __forceinline__ void cpa16(unsigned dst, const void* src) {
    asm volatile("cp.async.cg.shared.global [%0], [%1], 16;" :: "r"(dst), "l"(src));
}
#define CP_COMMIT() asm volatile("cp.async.commit_group;" ::: "memory")
#define CP_WAIT1()  asm volatile("cp.async.wait_group 1;" ::: "memory")
#define CP_WAIT0()  asm volatile("cp.async.wait_group 0;" ::: "memory")

// ---------------------------------------------------------------------------
// Mask dtype sniffing + bit-pack (bool arrives as int32).
// ---------------------------------------------------------------------------
__global__ void detect_mask(const void* __restrict__ mask)
{
    if (threadIdx.x != 0 || blockIdx.x != 0) return;
    const unsigned* w = (const unsigned*)mask;
    bool is_i32 = true, is_f32 = true;
    for (int i = 0; i < 1024; i++) {
        unsigned v = w[i];
        if (v != 0u && v != 1u)           is_i32 = false;
        if (v != 0u && v != 0x3F800000u)  is_f32 = false;
    }
    g_mask_mode = is_i32 ? 1 : (is_f32 ? 2 : 0);
}

__global__ __launch_bounds__(256) void convert_mask(const void* __restrict__ mask)
{
    const int mode = g_mask_mode;
    const int nw = Tn*Tn/32;
    int i = blockIdx.x*blockDim.x + threadIdx.x;
    int stride = gridDim.x*blockDim.x;
    if (mode == 1) {
        const int4* m = (const int4*)mask;
        for (; i < nw; i += stride) {
            unsigned w = 0;
            #pragma unroll
            for (int j = 0; j < 8; j++) {
                int4 v = m[(size_t)i*8 + j];
                w |= (v.x != 0 ? 1u : 0u) << (4*j);
                w |= (v.y != 0 ? 1u : 0u) << (4*j+1);
                w |= (v.z != 0 ? 1u : 0u) << (4*j+2);
                w |= (v.w != 0 ? 1u : 0u) << (4*j+3);
            }
            g_mbits[i] = w;
        }
    } else if (mode == 2) {
        const float4* m = (const float4*)mask;
        for (; i < nw; i += stride) {
            unsigned w = 0;
            #pragma unroll
            for (int j = 0; j < 8; j++) {
                float4 v = m[(size_t)i*8 + j];
                w |= (v.x != 0.0f ? 1u : 0u) << (4*j);
                w |= (v.y != 0.0f ? 1u : 0u) << (4*j+1);
                w |= (v.z != 0.0f ? 1u : 0u) << (4*j+2);
                w |= (v.w != 0.0f ? 1u : 0u) << (4*j+3);
            }
            g_mbits[i] = w;
        }
    } else {
        const uchar* m = (const uchar*)mask;
        for (; i < nw; i += stride) {
            unsigned w = 0;
            #pragma unroll
            for (int j = 0; j < 32; j++)
                w |= (m[(size_t)i*32 + j] != 0 ? 1u : 0u) << j;
            g_mbits[i] = w;
        }
    }
}

// ---------------------------------------------------------------------------
// tf32 MMA projection GEMM core (validated round 12).
// ---------------------------------------------------------------------------
__device__ __forceinline__ void mma_gemm_core(
    const float* __restrict__ X, const float* __restrict__ W,
    float* Xs, float* Bt, int m0, int n0, float acc[8][4])
{
    const int tid = threadIdx.x;
    const int lane = tid & 31, wid = tid >> 5;
    const int lr = lane & 7, sub = lane >> 3, c01 = sub & 1;
    const int qw = wid * 16;
    const unsigned aXb = sm_u32(Xs + (qw + lr + c01*8)*68 + (sub>>1)*4);
    unsigned bWb[4]; int eW[4];
    #pragma unroll
    for (int p = 0; p < 4; p++) {
        int brow = (2*p + (sub>>1))*8 + lr;
        bWb[p] = sm_u32(Bt + brow*64);
        eW[p]  = brow & 7;
    }

    for (int k0 = 0; k0 < Dn; k0 += 64) {
        float4 xv[8];
        #pragma unroll
        for (int r = 0; r < 8; r++) {
            int i = tid + 256*r;
            int rr = i >> 4, c = i & 15;
            xv[r] = ((const float4*)X)[(size_t)(m0+rr)*(Dn/4) + (k0>>2) + c];
        }
        float4 wv[4];
        #pragma unroll
        for (int it = 0; it < 4; it++) {
            int k = (tid & 31) + 32*(it & 1);
            int c = (tid >> 5) + 8*(it >> 1);
            wv[it] = *(const float4*)(W + (size_t)(k0+k)*Dn + n0 + 4*c);
        }
        __syncthreads();
        #pragma unroll
        for (int r = 0; r < 8; r++) {
            int i = tid + 256*r;
            int rr = i >> 4, c = i & 15;
            float4 v = xv[r];
            v.x = tf32r(v.x); v.y = tf32r(v.y); v.z = tf32r(v.z); v.w = tf32r(v.w);
            *(float4*)(Xs + rr*68 + 4*c) = v;
        }
        #pragma unroll
        for (int it = 0; it < 4; it++) {
            int k = (tid & 31) + 32*(it & 1);
            int c = (tid >> 5) + 8*(it >> 1);
            float e[4] = {tf32r(wv[it].x), tf32r(wv[it].y), tf32r(wv[it].z), tf32r(wv[it].w)};
            #pragma unroll
            for (int z = 0; z < 4; z++) {
                int n = 4*c + z;
                Bt[n*64 + 4*((k>>2)^(n&7)) + (k&3)] = e[z];
            }
        }
        __syncthreads();
        #pragma unroll
        for (int kk = 0; kk < 8; kk++) {
            unsigned a0,a1,a2,a3;
            ldsm4(a0,a1,a2,a3, aXb + kk*32);
            #pragma unroll
            for (int p = 0; p < 4; p++) {
                unsigned b0,b1,b2,b3;
                unsigned ofs = (unsigned)(((2*kk + c01) ^ eW[p]) << 4);
                ldsm4(b0,b1,b2,b3, bWb[p] + ofs);
                mma_tf32(acc[2*p],   a0,a1,a2,a3, b0,b1);
                mma_tf32(acc[2*p+1], a0,a1,a2,a3, b2,b3);
            }
        }
    }
}

#define GEMM_SMEM ((128*68 + 64*64) * 4)

__global__ __launch_bounds__(256) void qkv_gemm(
    const float* __restrict__ X,
    const float* __restrict__ Wq, const float* __restrict__ Wk, const float* __restrict__ Wv,
    const float* __restrict__ bq, const float* __restrict__ bk, const float* __restrict__ bv)
{
    extern __shared__ float smg[];
    float* Xs = smg;              // [128][68]
    float* Bt = smg + 128*68;     // [64][64] swizzled W^T

    const float* W; const float* bias;
    if      (blockIdx.z == 0) { W = Wq; bias = bq; }
    else if (blockIdx.z == 1) { W = Wk; bias = bk; }
    else                      { W = Wv; bias = bv; }

    const int m0 = blockIdx.y * 128, n0 = blockIdx.x * 64;
    float acc[8][4] = {};
    mma_gemm_core(X, W, Xs, Bt, m0, n0, acc);

    const int lane = threadIdx.x & 31, wid = threadIdx.x >> 5;
    const int gp = lane >> 2, tg = lane & 3;
    const int h = blockIdx.x;     // 64-wide n tile = one head
    const int m_a = m0 + wid*16 + gp, m_b = m_a + 8;
    const int ba = m_a >> 12, ta = m_a & (Tn-1);
    const int bb = m_b >> 12, tb = m_b & (Tn-1);
    const int bha = ba*Hn + h, bhb = bb*Hn + h;

    if (blockIdx.z == 2) {
        // V: tf32-rounded, TRANSPOSED store g_V[bh][dh][t]
        #pragma unroll
        for (int nt = 0; nt < 8; nt++) {
            int dh = nt*8 + 2*tg;
            float bx = bias[n0 + dh], by = bias[n0 + dh + 1];
            g_V[((size_t)bha*DHn + dh  )*Tn + ta] = tf32r(acc[nt][0]+bx);
            g_V[((size_t)bha*DHn + dh+1)*Tn + ta] = tf32r(acc[nt][1]+by);
            g_V[((size_t)bhb*DHn + dh  )*Tn + tb] = tf32r(acc[nt][2]+bx);
            g_V[((size_t)bhb*DHn + dh+1)*Tn + tb] = tf32r(acc[nt][3]+by);
        }
    } else {
        float* out = (blockIdx.z == 0) ? g_Q : g_K;
        const float sc = (blockIdx.z == 0) ? 0.125f : 1.0f;
        float* oa = out + ((size_t)bha*Tn + ta)*DHn;
        float* ob = out + ((size_t)bhb*Tn + tb)*DHn;
        #pragma unroll
        for (int nt = 0; nt < 8; nt++) {
            int dh = nt*8 + 2*tg;
            float bx = bias[n0 + dh], by = bias[n0 + dh + 1];
            *(float2*)(oa + dh) = make_float2(tf32r((acc[nt][0]+bx)*sc), tf32r((acc[nt][1]+by)*sc));
            *(float2*)(ob + dh) = make_float2(tf32r((acc[nt][2]+bx)*sc), tf32r((acc[nt][3]+by)*sc));
        }
    }
}

__global__ __launch_bounds__(256) void out_gemm(
    const float* __restrict__ W, const float* __restrict__ bias, float* __restrict__ out)
{
    extern __shared__ float smg[];
    float* Xs = smg;
    float* Bt = smg + 128*68;

    const int m0 = blockIdx.y * 128, n0 = blockIdx.x * 64;
    float acc[8][4] = {};
    mma_gemm_core(g_AO, W, Xs, Bt, m0, n0, acc);

    const int lane = threadIdx.x & 31, wid = threadIdx.x >> 5;
    const int gp = lane >> 2, tg = lane & 3;
    const int m_a = m0 + wid*16 + gp, m_b = m_a + 8;
    #pragma unroll
    for (int nt = 0; nt < 8; nt++) {
        int n = n0 + nt*8 + 2*tg;
        float bx = bias[n], by = bias[n+1];
        *(float2*)(out + (size_t)m_a*Dn + n) = make_float2(acc[nt][0]+bx, acc[nt][1]+by);
        *(float2*)(out + (size_t)m_b*Dn + n) = make_float2(acc[nt][2]+bx, acc[nt][3]+by);
    }
}

// ---------------------------------------------------------------------------
// Flash attention v7: tf32 mma + ldmatrix + cp.async double-buffered K/V.
// All data transforms (tf32 round, 1/8 scale, V transpose) done in qkv_gemm,
// so tile loads are pure 16B cp.async copies into the final smem layouts.
// ---------------------------------------------------------------------------
#define AQ 128
#define AK 64
#define SQ 68
#define KS_STRIDE (AK*SQ)      // floats per K stage (4352)
#define VT_STRIDE (AK*64)      // floats per V stage (4096)

__global__ __launch_bounds__(256) void attn_kernel()
{
    extern __shared__ float sm[];
    float* Qs  = sm;                       // [128][68]
    float* Ks2 = Qs + AQ*SQ;               // [2][64][68]
    float* Vt2 = Ks2 + 2*KS_STRIDE;        // [2][64][64] swizzled

    const int tid  = threadIdx.x;
    const int lane = tid & 31, wid = tid >> 5;
    const int gp = lane >> 2, tg = lane & 3;
    const int qw = wid * 16;
    const int bh = blockIdx.y;
    const int q0 = blockIdx.x * AQ;

    const int lr = lane & 7, sub = lane >> 3, c01 = sub & 1;
    const unsigned aQb = sm_u32(Qs + (qw + lr + c01*8)*SQ + (sub>>1)*4);
    unsigned bKb[4], bVb[4];
    int eV[4];
    #pragma unroll
    for (int p = 0; p < 4; p++) {
        int brow = (2*p + (sub >> 1))*8 + lr;
        bKb[p] = sm_u32(Ks2 + brow*SQ + c01*4);
        bVb[p] = sm_u32(Vt2 + brow*64);
        eV[p]  = brow & 7;
    }

    const unsigned ksB = sm_u32(Ks2);
    const unsigned vtB = sm_u32(Vt2);
    const char* Kg = (const char*)(g_K + ((size_t)bh*Tn)*DHn);
    const char* Vg = (const char*)(g_V + ((size_t)bh*DHn)*Tn);

    // prefetch helper (K tile + V tile for key block j0 -> stage buf)
    auto prefetch = [&](int j0, int buf) {
        const char* kp = Kg + (size_t)j0*DHn*4;
        unsigned kd = ksB + buf*(KS_STRIDE*4);
        #pragma unroll
        for (int r = 0; r < 4; r++) {
            int i = tid + 256*r;
            int row = i >> 4, c = i & 15;
            cpa16(kd + row*(SQ*4) + c*16, kp + row*256 + c*16);
        }
        unsigned vd = vtB + buf*(VT_STRIDE*4);
        #pragma unroll
        for (int r = 0; r < 4; r++) {
            int i = tid + 256*r;
            int d = i >> 4, c = i & 15;
            cpa16(vd + d*256 + 16*(c ^ (d & 7)), Vg + ((size_t)d*Tn + j0)*4 + c*16);
        }
    };

    // ---- prologue: Q copy (cp.async) + first two K/V tiles ----
    {
        const char* qp = (const char*)(g_Q + ((size_t)bh*Tn + q0)*DHn);
        unsigned qd = sm_u32(Qs);
        #pragma unroll
        for (int r = 0; r < 8; r++) {
            int i = tid + 256*r;
            int row = i >> 4, c = i & 15;
            cpa16(qd + row*(SQ*4) + c*16, qp + row*256 + c*16);
        }
        prefetch(0, 0);
        CP_COMMIT();          // group: Q + tile0
        prefetch(AK, 1);
        CP_COMMIT();          // group: tile1
    }

    const int r0 = qw + gp, r1 = r0 + 8;
    float m0r = -1e30f, m1r = -1e30f, l0r = 0.0f, l1r = 0.0f;
    float o[8][4] = {};

    for (int it = 0; it < Tn/AK; it++) {
        const int j0 = it*AK;
        const int buf = it & 1;
        const unsigned kofs = buf*(KS_STRIDE*4);
        const unsigned vofs = buf*(VT_STRIDE*4);

        CP_WAIT1();
        __syncthreads();   // tile `it` data visible to all warps

        // mask words early (independent LDGs overlap the S MMAs)
        const unsigned* Mb0 = g_mbits + (size_t)(q0 + r0)*(Tn/32) + (j0 >> 5);
        const unsigned* Mb1 = Mb0 + (size_t)8*(Tn/32);
        unsigned w0a = Mb0[0], w0b = Mb0[1];
        unsigned w1a = Mb1[0], w1b = Mb1[1];

        // ---- S = Q K^T ----
        float s[8][4] = {};
        #pragma unroll
        for (int kk = 0; kk < 8; kk++) {
            unsigned a0, a1, a2, a3;
            ldsm4(a0, a1, a2, a3, aQb + kk*32);
            #pragma unroll
            for (int p = 0; p < 4; p++) {
                unsigned b0, b1, b2, b3;
                ldsm4(b0, b1, b2, b3, bKb[p] + kofs + kk*32);
                mma_tf32(s[2*p],   a0, a1, a2, a3, b0, b1);
                mma_tf32(s[2*p+1], a0, a1, a2, a3, b2, b3);
            }
        }

        // ---- mask + row max ----
        float mx0 = -1e30f, mx1 = -1e30f;
        #pragma unroll
        for (int nt = 0; nt < 8; nt++) {
            unsigned wr0 = (nt < 4) ? w0a : w0b;
            unsigned wr1 = (nt < 4) ? w1a : w1b;
            int sh = (nt & 3)*8 + 2*tg;
            if (!((wr0 >> sh) & 1))       s[nt][0] -= 1e9f;
            if (!((wr0 >> (sh+1)) & 1))   s[nt][1] -= 1e9f;
            if (!((wr1 >> sh) & 1))       s[nt][2] -= 1e9f;
            if (!((wr1 >> (sh+1)) & 1))   s[nt][3] -= 1e9f;
            mx0 = fmaxf(mx0, fmaxf(s[nt][0], s[nt][1]));
            mx1 = fmaxf(mx1, fmaxf(s[nt][2], s[nt][3]));
        }
        mx0 = fmaxf(mx0, __shfl_xor_sync(0xffffffffu, mx0, 1));
        mx0 = fmaxf(mx0, __shfl_xor_sync(0xffffffffu, mx0, 2));
        mx1 = fmaxf(mx1, __shfl_xor_sync(0xffffffffu, mx1, 1));
        mx1 = fmaxf(mx1, __shfl_xor_sync(0xffffffffu, mx1, 2));

        float mn0 = fmaxf(m0r, mx0), mn1 = fmaxf(m1r, mx1);

        // ---- exp, partial row sums ----
        float l0 = 0.0f, l1 = 0.0f;
        #pragma unroll
        for (int nt = 0; nt < 8; nt++) {
            s[nt][0] = __expf(s[nt][0] - mn0);
            s[nt][1] = __expf(s[nt][1] - mn0);
            s[nt][2] = __expf(s[nt][2] - mn1);
            s[nt][3] = __expf(s[nt][3] - mn1);
            l0 += s[nt][0] + s[nt][1];
            l1 += s[nt][2] + s[nt][3];
        }
        l0 += __shfl_xor_sync(0xffffffffu, l0, 1);
        l0 += __shfl_xor_sync(0xffffffffu, l0, 2);
        l1 += __shfl_xor_sync(0xffffffffu, l1, 1);
        l1 += __shfl_xor_sync(0xffffffffu, l1, 2);

        float c0 = __expf(m0r - mn0);
        float c1 = __expf(m1r - mn1);
        m0r = mn0; m1r = mn1;
        l0r = l0r*c0 + l0;
        l1r = l1r*c1 + l1;

        // ---- O = O*corr + P V ----
        #pragma unroll
        for (int nt = 0; nt < 8; nt++) {
            o[nt][0] *= c0; o[nt][1] *= c0;
            o[nt][2] *= c1; o[nt][3] *= c1;
        }
        const int src1 = (lane & 28) | (tg >> 1);
        const int src2 = src1 | 2;
        const bool odd = tg & 1;
        #pragma unroll
        for (int kk = 0; kk < 8; kk++) {
            float v0 = __shfl_sync(0xffffffffu, s[kk][0], src1);
            float v1 = __shfl_sync(0xffffffffu, s[kk][1], src1);
            float v2 = __shfl_sync(0xffffffffu, s[kk][2], src1);
            float v3 = __shfl_sync(0xffffffffu, s[kk][3], src1);
            float u0 = __shfl_sync(0xffffffffu, s[kk][0], src2);
            float u1 = __shfl_sync(0xffffffffu, s[kk][1], src2);
            float u2 = __shfl_sync(0xffffffffu, s[kk][2], src2);
            float u3 = __shfl_sync(0xffffffffu, s[kk][3], src2);
            unsigned a0 = fbits(tf32r(odd ? v1 : v0));
            unsigned a1 = fbits(tf32r(odd ? v3 : v2));
            unsigned a2 = fbits(tf32r(odd ? u1 : u0));
            unsigned a3 = fbits(tf32r(odd ? u3 : u2));
            #pragma unroll
            for (int p = 0; p < 4; p++) {
                unsigned b0, b1, b2, b3;
                unsigned ofs = (unsigned)(((2*kk + c01) ^ eV[p]) << 4);
                ldsm4(b0, b1, b2, b3, bVb[p] + vofs + ofs);
                mma_tf32(o[2*p],   a0, a1, a2, a3, b0, b1);
                mma_tf32(o[2*p+1], a0, a1, a2, a3, b2, b3);
            }
        }

        __syncthreads();   // all warps done reading stage `buf`
        if (it + 2 < Tn/AK) prefetch(j0 + 2*AK, buf);
        CP_COMMIT();       // commit (possibly empty) group to keep count in step
    }
    CP_WAIT0();

    // ---- finalize: normalize, write head-interleaved [b][t][d] ----
    const int b = bh >> 3, h = bh & 7;
    float inv0 = 1.0f / l0r;
    float inv1 = 1.0f / l1r;
    float* O0 = g_AO + ((size_t)(b*Tn + q0 + r0))*Dn + h*DHn;
    float* O1 = g_AO + ((size_t)(b*Tn + q0 + r1))*Dn + h*DHn;
    #pragma unroll
    for (int nt = 0; nt < 8; nt++) {
        int col = nt*8 + 2*tg;
        *(float2*)(O0 + col) = make_float2(o[nt][0]*inv0, o[nt][1]*inv0);
        *(float2*)(O1 + col) = make_float2(o[nt][2]*inv1, o[nt][3]*inv1);
    }
}

// ---------------------------------------------------------------------------
extern "C" void kernel_launch(void* const* d_in, const int* in_sizes, int n_in,
                              void* d_out, int out_size)
{
    const float* x  = (const float*)d_in[0];
    const float* Wq = (const float*)d_in[1];
    const float* bq = (const float*)d_in[2];
    const float* Wk = (const float*)d_in[3];
    const float* bk = (const float*)d_in[4];
    const float* Wv = (const float*)d_in[5];
    const float* bv = (const float*)d_in[6];
    const float* Wo = (const float*)d_in[7];
    const float* bo = (const float*)d_in[8];
    const void*  mask = (const void*)d_in[9];
    float* out = (float*)d_out;

    const int attn_smem = (AQ*SQ + 2*KS_STRIDE + 2*VT_STRIDE) * 4;  // 102,400 B
    cudaFuncSetAttribute(attn_kernel, cudaFuncAttributeMaxDynamicSharedMemorySize, attn_smem);
    cudaFuncSetAttribute(qkv_gemm, cudaFuncAttributeMaxDynamicSharedMemorySize, GEMM_SMEM);
    cudaFuncSetAttribute(out_gemm, cudaFuncAttributeMaxDynamicSharedMemorySize, GEMM_SMEM);

    detect_mask<<<1, 32>>>(mask);
    convert_mask<<<2048, 256>>>(mask);
    qkv_gemm<<<dim3(Dn/64, (Bn*Tn)/128, 3), 256, GEMM_SMEM>>>(x, Wq, Wk, Wv, bq, bk, bv);
    attn_kernel<<<dim3(Tn/AQ, BHn), 256, attn_smem>>>();
    out_gemm<<<dim3(Dn/64, (Bn*Tn)/128), 256, GEMM_SMEM>>>(Wo, bo, out);
}